// round 15
// baseline (speedup 1.0000x reference)
#include <cuda_runtime.h>
#include <cuda_fp16.h>
#include <math.h>
#include <stdint.h>

#define B   256
#define T1  127
#define D   512
#define H   512
#define G   2048
#define NL  3
#define GH  (G * H)
#define OUT_ENC ((size_t)B * T1 * D)

#define GRID 128
#define NT   256     // pre_gemm block
#define NTL  128     // lstm block: 4 warps, 32 rows each

typedef __half hf;

// ---------------------------------------------------------------------------
// Scratch
// ---------------------------------------------------------------------------
__device__ float g_pre0[(size_t)T1 * B * G];   // [t][b][tilen*32 + q*8 + j]
__device__ hf g_h[2][NL][B * H];               // wave-parity double buffer
__device__ hf g_wih[NL * GH];
__device__ hf g_whh[NL * GH];
__device__ hf g_x[(size_t)B * T1 * D];
__device__ unsigned g_flagsh[GRID];
__device__ unsigned g_relh[2];

__device__ __forceinline__ float sigm(float x) { return 1.f / (1.f + expf(-x)); }

// ---------------------------------------------------------------------------
// Per-half grid barrier: the two m-halves (64 CTAs each) are independent.
// ---------------------------------------------------------------------------
__device__ __forceinline__ void gbarh(unsigned gen, int m) {
    __syncthreads();
    if (threadIdx.x == 0) {
        __threadfence();
        ((volatile unsigned*)g_flagsh)[blockIdx.x] = gen;
    }
    if ((blockIdx.x & 63) == 0) {
        if (threadIdx.x < 64)
            while ((int)(((volatile unsigned*)g_flagsh)[(blockIdx.x & 64)
                         + threadIdx.x] - gen) < 0) {}
        __syncthreads();
        if (threadIdx.x == 0) {
            __threadfence();
            *(volatile unsigned*)&g_relh[m] = gen;
        }
    }
    while ((int)(*(volatile unsigned*)&g_relh[m] - gen) < 0) {}
    __threadfence();
    __syncthreads();
}

// ---------------------------------------------------------------------------
__device__ __forceinline__ void cp16u(uint32_t dst, const hf* src) {
    asm volatile("cp.async.cg.shared.global [%0], [%1], 16;" :: "r"(dst), "l"(src));
}
#define CP_COMMIT()  asm volatile("cp.async.commit_group;" ::: "memory")
#define CP_WAIT1()   asm volatile("cp.async.wait_group 1;" ::: "memory")
#define CP_WAIT2()   asm volatile("cp.async.wait_group 2;" ::: "memory")
#define CP_WAITALL() asm volatile("cp.async.wait_group 0;" ::: "memory")

__device__ __forceinline__ void ldm4(uint32_t addr, uint32_t r[4]) {
    asm volatile("ldmatrix.sync.aligned.m8n8.x4.shared.b16 {%0,%1,%2,%3}, [%4];"
                 : "=r"(r[0]), "=r"(r[1]), "=r"(r[2]), "=r"(r[3]) : "r"(addr));
}
__device__ __forceinline__ void mma16816(float c[4], const uint32_t a[4],
                                         uint32_t b0, uint32_t b1) {
    asm volatile(
        "mma.sync.aligned.m16n8k16.row.col.f32.f16.f16.f32 "
        "{%0,%1,%2,%3},{%4,%5,%6,%7},{%8,%9},{%0,%1,%2,%3};"
        : "+f"(c[0]), "+f"(c[1]), "+f"(c[2]), "+f"(c[3])
        : "r"(a[0]), "r"(a[1]), "r"(a[2]), "r"(a[3]), "r"(b0), "r"(b1));
}
__device__ __forceinline__ void pfL2(const void* p) {
    asm volatile("prefetch.global.L2 [%0];" :: "l"(p));
}

// ---------------------------------------------------------------------------
// pre_gemm (64x64 tile, streams A+B) — unchanged
// ---------------------------------------------------------------------------
#define STG_BYTES 16384
#define PLANE_B   8192

__device__ __forceinline__ void stage_chunk(const hf* __restrict__ A, int lda,
                                            const hf* __restrict__ W, int colbase,
                                            uint32_t st) {
    const int tid = threadIdx.x;
#pragma unroll
    for (int u = 0; u < 4; u++) {
        int id = tid + u * NT;
        int pl = id >> 9, rm = id & 511;
        int r = rm >> 3, s = rm & 7;
        uint32_t dst = st + (uint32_t)(pl * PLANE_B + r * 128 + ((s ^ (r & 7)) * 16));
        const hf* sp;
        if (pl == 0) {
            sp = A + (size_t)r * lda + s * 8;
        } else {
            int wrow = ((r >> 4) << 9) + colbase + (r & 15);
            sp = W + (size_t)wrow * 512 + s * 8;
        }
        cp16u(dst, sp);
    }
}

__device__ __forceinline__ void chunk_compute64(uint32_t sb, int arow, int ahalf,
                                                int nrl, int bhalf, float acc[4][4]) {
#pragma unroll
    for (int sub = 0; sub < 4; sub++) {
        uint32_t a[4];
        int aseg = (sub * 2 + ahalf) ^ (arow & 7);
        ldm4(sb + (uint32_t)(arow * 128 + aseg * 16), a);
        uint32_t b0[4], b1[4];
        {
            int nr = nrl;
            int bseg = (sub * 2 + bhalf) ^ (nr & 7);
            ldm4(sb + (uint32_t)(PLANE_B + nr * 128 + bseg * 16), b0);
        }
        {
            int nr = nrl + 16;
            int bseg = (sub * 2 + bhalf) ^ (nr & 7);
            ldm4(sb + (uint32_t)(PLANE_B + nr * 128 + bseg * 16), b1);
        }
        mma16816(acc[0], a, b0[0], b0[1]);
        mma16816(acc[1], a, b0[2], b0[3]);
        mma16816(acc[2], a, b1[0], b1[1]);
        mma16816(acc[3], a, b1[2], b1[3]);
    }
}

// ---------------------------------------------------------------------------
__global__ void split_w_kernel(const float* __restrict__ wih,
                               const float* __restrict__ whh) {
    int idx = blockIdx.x * blockDim.x + threadIdx.x;
    if (idx >= NL * GH) return;
    g_wih[idx] = __float2half(wih[idx]);
    g_whh[idx] = __float2half(whh[idx]);
}

// ---------------------------------------------------------------------------
// attn[b,d] = softmax_d( sum_t x[b,t,d]*attn_w[2H+t] )  — time-invariant.
// ---------------------------------------------------------------------------
__global__ void attn_kernel(const float* __restrict__ x, const float* __restrict__ aw,
                            float* __restrict__ out) {
    __shared__ float saw[T1];
    __shared__ float red[512];
    int b = blockIdx.x, d = threadIdx.x;
    if (d < T1) saw[d] = aw[2 * H + d];
    __syncthreads();
    const float* xb = x + (size_t)b * T1 * D;
    float acc = 0.f;
    for (int t = 0; t < T1; t++) acc += xb[(size_t)t * D + d] * saw[t];
    red[d] = acc;
    __syncthreads();
    for (int s = 256; s > 0; s >>= 1) {
        if (d < s) red[d] = fmaxf(red[d], red[d + s]);
        __syncthreads();
    }
    float mx = red[0];
    __syncthreads();
    float e = expf(acc - mx);
    red[d] = e;
    __syncthreads();
    for (int s = 256; s > 0; s >>= 1) {
        if (d < s) red[d] += red[d + s];
        __syncthreads();
    }
    float a = e / red[0];
    float* ob = out + (size_t)b * T1 * D;
    for (int t = 0; t < T1; t++) {
        float w = a * xb[(size_t)t * D + d];
        ob[(size_t)t * D + d] = w;
        g_x[(size_t)b * T1 * D + (size_t)t * D + d] = __float2half(w);
    }
}

// ---------------------------------------------------------------------------
// pre0: [t][b][tilen*32 + q*8 + j] = weighted@Wih0^T + b_ih0 + b_hh0
// ---------------------------------------------------------------------------
__global__ void __launch_bounds__(NT) pre_gemm_kernel(const float* __restrict__ bih,
                                                      const float* __restrict__ bhh) {
    __shared__ __align__(128) char ring[3 * STG_BYTES];
    int tstep = blockIdx.x >> 2;
    int b0    = (blockIdx.x & 3) * 64;
    int tilec = blockIdx.y;
    int colbase = tilec * 16;
    const int lane = threadIdx.x & 31, warp = threadIdx.x >> 5;
    const int arow  = (warp >> 1) * 16 + (lane & 15);
    const int ahalf = lane >> 4;
    const int nrl   = (warp & 1) * 32 + ((lane >> 4) << 3) + (lane & 7);
    const int bhalf = (lane >> 3) & 1;
    const uint32_t sbase = (uint32_t)__cvta_generic_to_shared(ring);
    const hf* A0 = g_x + (size_t)tstep * D + (size_t)b0 * (T1 * D);

    float acc[4][4] = {};
    stage_chunk(A0, T1 * D, g_wih, colbase, sbase);
    CP_COMMIT();
    stage_chunk(A0 + 64, T1 * D, g_wih + 64, colbase, sbase + STG_BYTES);
    CP_COMMIT();
    for (int kc = 0; kc < 8; kc++) {
        CP_WAIT1();
        __syncthreads();
        if (kc + 2 < 8)
            stage_chunk(A0 + (kc + 2) * 64, T1 * D, g_wih + (kc + 2) * 64, colbase,
                        sbase + ((kc + 2) % 3) * STG_BYTES);
        CP_COMMIT();
        chunk_compute64(sbase + (uint32_t)((kc % 3) * STG_BYTES),
                        arow, ahalf, nrl, bhalf, acc);
    }
    __syncthreads();

    size_t base = (size_t)tstep * B * G;
#pragma unroll
    for (int nt = 0; nt < 4; nt++)
#pragma unroll
        for (int e = 0; e < 4; e++) {
            int r = (warp >> 1) * 16 + (lane >> 2) + ((e >> 1) ? 8 : 0);
            int c = (warp & 1) * 32 + nt * 8 + (lane & 3) * 2 + (e & 1);
            int bcol = ((c >> 4) << 9) + colbase + (c & 15);
            int idx = (tilec * 2 + ((c >> 3) & 1)) * 32 + ((c >> 4) << 3) + (c & 7);
            g_pre0[base + (size_t)(b0 + r) * G + idx] =
                acc[nt][e] + bih[bcol] + bhh[bcol];
        }
}

// ---------------------------------------------------------------------------
// Persistent wavefront kernel — 4 warps x (32 rows x 32 cols), per-warp
// independent pipelines (warp stages & LDSMs ONLY its own 32 A-rows; B from
// persistent SMEM weights, loaded by 4 warps -> half the B-LDSM of R14).
// 4-slot A ring, lookahead-3 (wait_group 2). pre0 L2-prefetched at wave start.
// ---------------------------------------------------------------------------
#define NCA    24
#define WSEG_B 32768
#define ASTG_B 16384

__global__ void __launch_bounds__(NTL, 1) lstm_kernel(const float* __restrict__ bih,
                                                      const float* __restrict__ bhh,
                                                      float* __restrict__ out) {
    __shared__ __align__(128) char wsm[5 * WSEG_B];    // 160KB persistent weights
    __shared__ __align__(128) char ring[4 * ASTG_B];   // 64KB A ring (4 slots)
    __shared__ float sbias[2][32];

    const int tid = threadIdx.x;
    const int warp = tid >> 5, lane = tid & 31;        // warp 0..3
    const int m     = blockIdx.x >> 6;        // 0..1 (independent halves)
    const int tilen = blockIdx.x & 63;        // 0..63
    const int row0    = m * 128;
    const int colbase = tilen * 8;
    const uint32_t wbase = (uint32_t)__cvta_generic_to_shared(wsm);
    const uint32_t rbase = (uint32_t)__cvta_generic_to_shared(ring);

    unsigned gen = *(volatile unsigned*)&g_relh[m];

    // zero both h parities for THIS half's rows (boundary waves read zeros)
    {
        const int HALF_E = 128 * H;
        for (int idx = (blockIdx.x & 63) * NTL + tid; idx < 2 * NL * HALF_E;
             idx += 64 * NTL) {
            int pl = idx / HALF_E;
            int rm = idx % HALF_E;
            ((hf*)g_h)[(size_t)pl * (B * H) + (size_t)row0 * H + rm] =
                __float2half(0.f);
        }
    }
    if (tid < 64) {
        int l = tid >> 5, c = tid & 31;
        int bcol = (l + 1) * G + ((c >> 3) << 9) + colbase + (c & 7);
        sbias[l][c] = bih[bcol] + bhh[bcol];
    }

    // one-time persistent weight load
    // seg: 0=Whh0 1=Whh1 2=Wih1 3=Whh2 4=Wih2 ; layout [seg][kchunk8][32r][64k]
    {
        const hf* wsrc[5] = { g_whh, g_whh + GH, g_wih + GH,
                              g_whh + 2 * GH, g_wih + 2 * GH };
#pragma unroll
        for (int it = 0; it < 80; it++) {
            int id = tid + it * NTL;         // 0..10239
            int s   = id >> 11;
            int rem = id & 2047;
            int c = rem >> 8;
            int r = (rem >> 3) & 31;
            int k = rem & 7;
            int wrow = ((r >> 3) << 9) + colbase + (r & 7);
            uint32_t dst = wbase + (uint32_t)(s * WSEG_B + c * 4096 + r * 128
                          + ((k ^ (r & 7)) * 16));
            cp16u(dst, wsrc[s] + (size_t)wrow * 512 + c * 64 + k * 8);
        }
        CP_COMMIT();
        CP_WAITALL();
        __syncthreads();
    }

    float cst[NL][8];
#pragma unroll
    for (int l = 0; l < NL; l++)
#pragma unroll
        for (int e = 0; e < 8; e++) cst[l][e] = 0.f;

    const int ar0   = warp * 32 + (lane & 15);
    const int ahalf = lane >> 4;
    const int nrl   = ((lane >> 4) << 3) + (lane & 7);
    const int bhalf = (lane >> 3) & 1;
    const int j0 = (lane & 3) * 2;

    gbarh(++gen, m);

    for (int w = 0; w < T1 + 2; w++) {
        const int np = w & 1, op = np ^ 1;
        const hf* agrp[3] = { g_h[op][0], g_h[op][1], g_h[op][2] };

        // prefetch pre0[t=w] rows into L2 (read by ew at wave end)
        if (w < T1) {
            const float* p = g_pre0 + (size_t)w * B * G + tilen * 32;
#pragma unroll
            for (int mt = 0; mt < 2; mt++)
#pragma unroll
                for (int er = 0; er < 2; er++) {
                    int row = row0 + warp * 32 + mt * 16 + (lane >> 2) + er * 8;
                    pfL2(p + (size_t)row * G);
                }
        }

        // warp-local staging: warp stages ONLY its 32 rows
        auto stageA = [&](int ac) {
            int grp = ac >> 3, g = ac & 7;
            const hf* src = agrp[grp] + (size_t)(row0 + warp * 32) * H + g * 64;
            uint32_t st = rbase + (uint32_t)((ac & 3) * ASTG_B + warp * 4096);
#pragma unroll
            for (int u = 0; u < 8; u++) {
                int id = lane + u * 32;        // 0..255
                int r = id >> 3, k = id & 7;
                cp16u(st + (uint32_t)(r * 128 + ((k ^ (r & 7)) * 16)),
                      src + (size_t)r * H + k * 8);
            }
        };

        auto body = [&](int ac, uint32_t segP, float (&aP)[2][4][4],
                        uint32_t segQ, float (&aQ)[2][4][4], bool two) {
            CP_WAIT2();
            __syncwarp();
            if (ac + 3 < NCA) stageA(ac + 3);
            CP_COMMIT();
            uint32_t sbA = rbase + (uint32_t)((ac & 3) * ASTG_B);
            int g = ac & 7;
            uint32_t sbP = wbase + segP * WSEG_B + (uint32_t)(g * 4096);
            uint32_t sbQ = wbase + segQ * WSEG_B + (uint32_t)(g * 4096);
#pragma unroll
            for (int sub = 0; sub < 4; sub++) {
                int aseg = (sub * 2 + ahalf) ^ (ar0 & 7);
                uint32_t a0[4], a1[4];
                ldm4(sbA + (uint32_t)(ar0 * 128 + aseg * 16), a0);
                ldm4(sbA + (uint32_t)((ar0 + 16) * 128 + aseg * 16), a1);
                int bs0 = (sub * 2 + bhalf) ^ (nrl & 7);
                int bs1 = (sub * 2 + bhalf) ^ ((nrl + 16) & 7);
                uint32_t b0[4], b1[4];
                ldm4(sbP + (uint32_t)(nrl * 128 + bs0 * 16), b0);
                ldm4(sbP + (uint32_t)((nrl + 16) * 128 + bs1 * 16), b1);
                if (two) {
                    uint32_t c0[4], c1[4];
                    ldm4(sbQ + (uint32_t)(nrl * 128 + bs0 * 16), c0);
                    ldm4(sbQ + (uint32_t)((nrl + 16) * 128 + bs1 * 16), c1);
                    mma16816(aP[0][0], a0, b0[0], b0[1]);
                    mma16816(aP[1][0], a1, b0[0], b0[1]);
                    mma16816(aQ[0][0], a0, c0[0], c0[1]);
                    mma16816(aQ[1][0], a1, c0[0], c0[1]);
                    mma16816(aP[0][1], a0, b0[2], b0[3]);
                    mma16816(aP[1][1], a1, b0[2], b0[3]);
                    mma16816(aQ[0][1], a0, c0[2], c0[3]);
                    mma16816(aQ[1][1], a1, c0[2], c0[3]);
                    mma16816(aP[0][2], a0, b1[0], b1[1]);
                    mma16816(aP[1][2], a1, b1[0], b1[1]);
                    mma16816(aQ[0][2], a0, c1[0], c1[1]);
                    mma16816(aQ[1][2], a1, c1[0], c1[1]);
                    mma16816(aP[0][3], a0, b1[2], b1[3]);
                    mma16816(aP[1][3], a1, b1[2], b1[3]);
                    mma16816(aQ[0][3], a0, c1[2], c1[3]);
                    mma16816(aQ[1][3], a1, c1[2], c1[3]);
                } else {
                    mma16816(aP[0][0], a0, b0[0], b0[1]);
                    mma16816(aP[1][0], a1, b0[0], b0[1]);
                    mma16816(aP[0][1], a0, b0[2], b0[3]);
                    mma16816(aP[1][1], a1, b0[2], b0[3]);
                    mma16816(aP[0][2], a0, b1[0], b1[1]);
                    mma16816(aP[1][2], a1, b1[0], b1[1]);
                    mma16816(aP[0][3], a0, b1[2], b1[3]);
                    mma16816(aP[1][3], a1, b1[2], b1[3]);
                }
            }
        };

        float acc0[2][4][4] = {}, acc1[2][4][4] = {}, acc2[2][4][4] = {};
        stageA(0);
        CP_COMMIT();
        stageA(1);
        CP_COMMIT();
        stageA(2);
        CP_COMMIT();
        // group 0: A=h0 -> Whh0(acc0) + Wih1(acc1)
        for (int ac = 0; ac < 8; ac++)   body(ac, 0u, acc0, 2u, acc1, true);
        // group 1: A=h1 -> Whh1(acc1) + Wih2(acc2)
        for (int ac = 8; ac < 16; ac++)  body(ac, 1u, acc1, 4u, acc2, true);
        // group 2: A=h2 -> Whh2(acc2)
        for (int ac = 16; ac < 24; ac++) body(ac, 3u, acc2, 3u, acc2, false);

        // register-resident cell update: l0@t=w, l1@t=w-1, l2@t=w-2
#pragma unroll
        for (int l = 0; l < NL; l++) {
            const int t = w - l;
            if (t < 0 || t >= T1) continue;
            float (&A)[2][4][4] = (l == 0) ? acc0 : (l == 1) ? acc1 : acc2;
#pragma unroll
            for (int mt = 0; mt < 2; mt++) {
                float add[4][2][2];   // [gate][er][ej]
                if (l == 0) {
                    const float* p = g_pre0 + (size_t)t * B * G + tilen * 32;
#pragma unroll
                    for (int er = 0; er < 2; er++) {
                        int row = row0 + warp * 32 + mt * 16 + (lane >> 2) + er * 8;
                        const float* pr = p + (size_t)row * G;
#pragma unroll
                        for (int q = 0; q < 4; q++) {
                            float2 v = *(const float2*)(pr + q * 8 + j0);
                            add[q][er][0] = v.x;
                            add[q][er][1] = v.y;
                        }
                    }
                } else {
#pragma unroll
                    for (int q = 0; q < 4; q++) {
                        float v0 = sbias[l - 1][q * 8 + j0];
                        float v1 = sbias[l - 1][q * 8 + j0 + 1];
                        add[q][0][0] = add[q][1][0] = v0;
                        add[q][0][1] = add[q][1][1] = v1;
                    }
                }
#pragma unroll
                for (int er = 0; er < 2; er++) {
                    hf h2v[2];
                    float hnf[2];
#pragma unroll
                    for (int ej = 0; ej < 2; ej++) {
                        int e = er * 2 + ej;
                        int ci = mt * 4 + er * 2 + ej;
                        float gi = A[mt][0][e] + add[0][er][ej];
                        float gf = A[mt][1][e] + add[1][er][ej];
                        float gg = A[mt][2][e] + add[2][er][ej];
                        float go = A[mt][3][e] + add[3][er][ej];
                        float i_ = sigm(gi), f_ = sigm(gf);
                        float g_ = tanhf(gg), o_ = sigm(go);
                        float cn = f_ * cst[l][ci] + i_ * g_;
                        float hn = o_ * tanhf(cn);
                        cst[l][ci] = cn;
                        h2v[ej] = __float2half(hn);
                        hnf[ej] = hn;
                    }
                    int row = row0 + warp * 32 + mt * 16 + (lane >> 2) + er * 8;
                    *(__half2*)&g_h[np][l][(size_t)row * H + colbase + j0] =
                        *(__half2*)h2v;
                    if (l == NL - 1)
                        *(float2*)(out + OUT_ENC + (size_t)row * T1 * H
                                   + (size_t)t * H + colbase + j0) =
                            make_float2(hnf[0], hnf[1]);
                }
            }
        }
        gbarh(++gen, m);
    }
}

// ---------------------------------------------------------------------------
extern "C" void kernel_launch(void* const* d_in, const int* in_sizes, int n_in,
                              void* d_out, int out_size) {
    const float* x   = (const float*)d_in[0];
    const float* wih = (const float*)d_in[1];
    const float* whh = (const float*)d_in[2];
    const float* bih = (const float*)d_in[3];
    const float* bhh = (const float*)d_in[4];
    const float* aw  = (const float*)d_in[5];
    float* out = (float*)d_out;

    split_w_kernel<<<(NL * GH + 255) / 256, 256>>>(wih, whh);
    attn_kernel<<<B, 512>>>(x, aw, out);
    dim3 pgrid(T1 * 4, G / 64);
    pre_gemm_kernel<<<pgrid, NT>>>(bih, bhh);
    lstm_kernel<<<GRID, NTL>>>(bih, bhh, out);
}

// round 16
// speedup vs baseline: 1.0514x; 1.0514x over previous
#include <cuda_runtime.h>
#include <cuda_fp16.h>
#include <math.h>
#include <stdint.h>

#define B   256
#define T1  127
#define D   512
#define H   512
#define G   2048
#define NL  3
#define GH  (G * H)
#define OUT_ENC ((size_t)B * T1 * D)

#define GRID 128
#define NT   256

typedef __half hf;

// ---------------------------------------------------------------------------
// Scratch
// ---------------------------------------------------------------------------
__device__ float g_pre0[(size_t)T1 * B * G];   // [t][b][tilen*32 + q*8 + j]
__device__ hf g_h[2][NL][B * H];               // wave-parity double buffer
__device__ hf g_wih[NL * GH];
__device__ hf g_whh[NL * GH];
__device__ hf g_x[(size_t)B * T1 * D];
__device__ unsigned g_flagsh[GRID];
__device__ unsigned g_relh[2];

__device__ __forceinline__ float sigm(float x) { return 1.f / (1.f + expf(-x)); }

// ---------------------------------------------------------------------------
// Per-half grid barrier: the two m-halves (64 CTAs each) are independent.
// ---------------------------------------------------------------------------
__device__ __forceinline__ void gbarh(unsigned gen, int m) {
    __syncthreads();
    if (threadIdx.x == 0) {
        __threadfence();
        ((volatile unsigned*)g_flagsh)[blockIdx.x] = gen;
    }
    if ((blockIdx.x & 63) == 0) {
        if (threadIdx.x < 64)
            while ((int)(((volatile unsigned*)g_flagsh)[(blockIdx.x & 64)
                         + threadIdx.x] - gen) < 0) {}
        __syncthreads();
        if (threadIdx.x == 0) {
            __threadfence();
            *(volatile unsigned*)&g_relh[m] = gen;
        }
    }
    while ((int)(*(volatile unsigned*)&g_relh[m] - gen) < 0) {}
    __threadfence();
    __syncthreads();
}

// ---------------------------------------------------------------------------
__device__ __forceinline__ void cp16u(uint32_t dst, const hf* src) {
    asm volatile("cp.async.cg.shared.global [%0], [%1], 16;" :: "r"(dst), "l"(src));
}
#define CP_COMMIT()  asm volatile("cp.async.commit_group;" ::: "memory")
#define CP_WAIT1()   asm volatile("cp.async.wait_group 1;" ::: "memory")
#define CP_WAIT2()   asm volatile("cp.async.wait_group 2;" ::: "memory")
#define CP_WAITALL() asm volatile("cp.async.wait_group 0;" ::: "memory")

__device__ __forceinline__ void ldm4(uint32_t addr, uint32_t r[4]) {
    asm volatile("ldmatrix.sync.aligned.m8n8.x4.shared.b16 {%0,%1,%2,%3}, [%4];"
                 : "=r"(r[0]), "=r"(r[1]), "=r"(r[2]), "=r"(r[3]) : "r"(addr));
}
__device__ __forceinline__ void mma16816(float c[4], const uint32_t a[4],
                                         uint32_t b0, uint32_t b1) {
    asm volatile(
        "mma.sync.aligned.m16n8k16.row.col.f32.f16.f16.f32 "
        "{%0,%1,%2,%3},{%4,%5,%6,%7},{%8,%9},{%0,%1,%2,%3};"
        : "+f"(c[0]), "+f"(c[1]), "+f"(c[2]), "+f"(c[3])
        : "r"(a[0]), "r"(a[1]), "r"(a[2]), "r"(a[3]), "r"(b0), "r"(b1));
}
__device__ __forceinline__ void pfL2(const void* p) {
    asm volatile("prefetch.global.L2 [%0];" :: "l"(p));
}

// ---------------------------------------------------------------------------
// pre_gemm (64x64 tile, streams A+B) — unchanged
// ---------------------------------------------------------------------------
#define STG_BYTES 16384
#define PLANE_B   8192

__device__ __forceinline__ void stage_chunk(const hf* __restrict__ A, int lda,
                                            const hf* __restrict__ W, int colbase,
                                            uint32_t st) {
    const int tid = threadIdx.x;
#pragma unroll
    for (int u = 0; u < 4; u++) {
        int id = tid + u * NT;
        int pl = id >> 9, rm = id & 511;
        int r = rm >> 3, s = rm & 7;
        uint32_t dst = st + (uint32_t)(pl * PLANE_B + r * 128 + ((s ^ (r & 7)) * 16));
        const hf* sp;
        if (pl == 0) {
            sp = A + (size_t)r * lda + s * 8;
        } else {
            int wrow = ((r >> 4) << 9) + colbase + (r & 15);
            sp = W + (size_t)wrow * 512 + s * 8;
        }
        cp16u(dst, sp);
    }
}

__device__ __forceinline__ void chunk_compute64(uint32_t sb, int arow, int ahalf,
                                                int nrl, int bhalf, float acc[4][4]) {
#pragma unroll
    for (int sub = 0; sub < 4; sub++) {
        uint32_t a[4];
        int aseg = (sub * 2 + ahalf) ^ (arow & 7);
        ldm4(sb + (uint32_t)(arow * 128 + aseg * 16), a);
        uint32_t b0[4], b1[4];
        {
            int nr = nrl;
            int bseg = (sub * 2 + bhalf) ^ (nr & 7);
            ldm4(sb + (uint32_t)(PLANE_B + nr * 128 + bseg * 16), b0);
        }
        {
            int nr = nrl + 16;
            int bseg = (sub * 2 + bhalf) ^ (nr & 7);
            ldm4(sb + (uint32_t)(PLANE_B + nr * 128 + bseg * 16), b1);
        }
        mma16816(acc[0], a, b0[0], b0[1]);
        mma16816(acc[1], a, b0[2], b0[3]);
        mma16816(acc[2], a, b1[0], b1[1]);
        mma16816(acc[3], a, b1[2], b1[3]);
    }
}

// ---------------------------------------------------------------------------
__global__ void split_w_kernel(const float* __restrict__ wih,
                               const float* __restrict__ whh) {
    int idx = blockIdx.x * blockDim.x + threadIdx.x;
    if (idx >= NL * GH) return;
    g_wih[idx] = __float2half(wih[idx]);
    g_whh[idx] = __float2half(whh[idx]);
}

// ---------------------------------------------------------------------------
// attn[b,d] = softmax_d( sum_t x[b,t,d]*attn_w[2H+t] )  — time-invariant.
// ---------------------------------------------------------------------------
__global__ void attn_kernel(const float* __restrict__ x, const float* __restrict__ aw,
                            float* __restrict__ out) {
    __shared__ float saw[T1];
    __shared__ float red[512];
    int b = blockIdx.x, d = threadIdx.x;
    if (d < T1) saw[d] = aw[2 * H + d];
    __syncthreads();
    const float* xb = x + (size_t)b * T1 * D;
    float acc = 0.f;
    for (int t = 0; t < T1; t++) acc += xb[(size_t)t * D + d] * saw[t];
    red[d] = acc;
    __syncthreads();
    for (int s = 256; s > 0; s >>= 1) {
        if (d < s) red[d] = fmaxf(red[d], red[d + s]);
        __syncthreads();
    }
    float mx = red[0];
    __syncthreads();
    float e = expf(acc - mx);
    red[d] = e;
    __syncthreads();
    for (int s = 256; s > 0; s >>= 1) {
        if (d < s) red[d] += red[d + s];
        __syncthreads();
    }
    float a = e / red[0];
    float* ob = out + (size_t)b * T1 * D;
    for (int t = 0; t < T1; t++) {
        float w = a * xb[(size_t)t * D + d];
        ob[(size_t)t * D + d] = w;
        g_x[(size_t)b * T1 * D + (size_t)t * D + d] = __float2half(w);
    }
}

// ---------------------------------------------------------------------------
// pre0: [t][b][tilen*32 + q*8 + j] = weighted@Wih0^T + b_ih0 + b_hh0
// ---------------------------------------------------------------------------
__global__ void __launch_bounds__(NT) pre_gemm_kernel(const float* __restrict__ bih,
                                                      const float* __restrict__ bhh) {
    __shared__ __align__(128) char ring[3 * STG_BYTES];
    int tstep = blockIdx.x >> 2;
    int b0    = (blockIdx.x & 3) * 64;
    int tilec = blockIdx.y;
    int colbase = tilec * 16;
    const int lane = threadIdx.x & 31, warp = threadIdx.x >> 5;
    const int arow  = (warp >> 1) * 16 + (lane & 15);
    const int ahalf = lane >> 4;
    const int nrl   = (warp & 1) * 32 + ((lane >> 4) << 3) + (lane & 7);
    const int bhalf = (lane >> 3) & 1;
    const uint32_t sbase = (uint32_t)__cvta_generic_to_shared(ring);
    const hf* A0 = g_x + (size_t)tstep * D + (size_t)b0 * (T1 * D);

    float acc[4][4] = {};
    stage_chunk(A0, T1 * D, g_wih, colbase, sbase);
    CP_COMMIT();
    stage_chunk(A0 + 64, T1 * D, g_wih + 64, colbase, sbase + STG_BYTES);
    CP_COMMIT();
    for (int kc = 0; kc < 8; kc++) {
        CP_WAIT1();
        __syncthreads();
        if (kc + 2 < 8)
            stage_chunk(A0 + (kc + 2) * 64, T1 * D, g_wih + (kc + 2) * 64, colbase,
                        sbase + ((kc + 2) % 3) * STG_BYTES);
        CP_COMMIT();
        chunk_compute64(sbase + (uint32_t)((kc % 3) * STG_BYTES),
                        arow, ahalf, nrl, bhalf, acc);
    }
    __syncthreads();

    size_t base = (size_t)tstep * B * G;
#pragma unroll
    for (int nt = 0; nt < 4; nt++)
#pragma unroll
        for (int e = 0; e < 4; e++) {
            int r = (warp >> 1) * 16 + (lane >> 2) + ((e >> 1) ? 8 : 0);
            int c = (warp & 1) * 32 + nt * 8 + (lane & 3) * 2 + (e & 1);
            int bcol = ((c >> 4) << 9) + colbase + (c & 15);
            int idx = (tilec * 2 + ((c >> 3) & 1)) * 32 + ((c >> 4) << 3) + (c & 7);
            g_pre0[base + (size_t)(b0 + r) * G + idx] =
                acc[nt][e] + bih[bcol] + bhh[bcol];
        }
}

// ---------------------------------------------------------------------------
// Persistent wavefront kernel — R14 structure (8 warps, 16-row warp tiles,
// per-warp independent pipelines, persistent SMEM weights, 4-slot lookahead-3
// ring, per-half barriers) + INTERLEAVED cell updates: ew(l) runs as soon as
// its accumulator completes (after chunk groups 8/16/24), overlapping ew's
// global-load latency with the remaining GEMM chunks. Tail = ew(l2) + barrier.
// ---------------------------------------------------------------------------
#define NCA    24
#define WSEG_B 32768
#define ASTG_B 16384

__global__ void __launch_bounds__(NT, 1) lstm_kernel(const float* __restrict__ bih,
                                                     const float* __restrict__ bhh,
                                                     float* __restrict__ out) {
    __shared__ __align__(128) char wsm[5 * WSEG_B];    // 160KB persistent weights
    __shared__ __align__(128) char ring[4 * ASTG_B];   // 64KB A ring (4 slots)
    __shared__ float sbias[2][32];

    const int tid = threadIdx.x;
    const int warp = tid >> 5, lane = tid & 31;
    const int m     = blockIdx.x >> 6;        // 0..1 (independent halves)
    const int tilen = blockIdx.x & 63;        // 0..63
    const int row0    = m * 128;
    const int colbase = tilen * 8;
    const uint32_t wbase = (uint32_t)__cvta_generic_to_shared(wsm);
    const uint32_t rbase = (uint32_t)__cvta_generic_to_shared(ring);

    unsigned gen = *(volatile unsigned*)&g_relh[m];

    // zero both h parities for THIS half's rows (boundary waves read zeros)
    {
        const int HALF_E = 128 * H;
        for (int idx = (blockIdx.x & 63) * NT + tid; idx < 2 * NL * HALF_E;
             idx += 64 * NT) {
            int pl = idx / HALF_E;
            int rm = idx % HALF_E;
            ((hf*)g_h)[(size_t)pl * (B * H) + (size_t)row0 * H + rm] =
                __float2half(0.f);
        }
    }
    if (tid < 64) {
        int l = tid >> 5, c = tid & 31;
        int bcol = (l + 1) * G + ((c >> 3) << 9) + colbase + (c & 7);
        sbias[l][c] = bih[bcol] + bhh[bcol];
    }

    // one-time persistent weight load
    // seg: 0=Whh0 1=Whh1 2=Wih1 3=Whh2 4=Wih2 ; layout [seg][kchunk8][32r][64k]
    {
        const hf* wsrc[5] = { g_whh, g_whh + GH, g_wih + GH,
                              g_whh + 2 * GH, g_wih + 2 * GH };
#pragma unroll
        for (int it = 0; it < 40; it++) {
            int id = tid + it * NT;          // 0..10239
            int s   = id >> 11;
            int rem = id & 2047;
            int c = rem >> 8;
            int r = (rem >> 3) & 31;
            int k = rem & 7;
            int wrow = ((r >> 3) << 9) + colbase + (r & 7);
            uint32_t dst = wbase + (uint32_t)(s * WSEG_B + c * 4096 + r * 128
                          + ((k ^ (r & 7)) * 16));
            cp16u(dst, wsrc[s] + (size_t)wrow * 512 + c * 64 + k * 8);
        }
        CP_COMMIT();
        CP_WAITALL();
        __syncthreads();
    }

    float cst[NL][4];
#pragma unroll
    for (int l = 0; l < NL; l++)
#pragma unroll
        for (int e = 0; e < 4; e++) cst[l][e] = 0.f;

    const int arow  = warp * 16 + (lane & 15);
    const int ahalf = lane >> 4;
    const int nrl   = ((lane >> 4) << 3) + (lane & 7);
    const int bhalf = (lane >> 3) & 1;
    const int rb = warp * 16 + (lane >> 2);
    const int j0 = (lane & 3) * 2;

    gbarh(++gen, m);

    for (int w = 0; w < T1 + 2; w++) {
        const int np = w & 1, op = np ^ 1;
        const hf* agrp[3] = { g_h[op][0], g_h[op][1], g_h[op][2] };

        // prefetch pre0[t=w] rows into L2 (read by ew(l0) mid-wave)
        if (w < T1) {
            const float* p = g_pre0 + (size_t)w * B * G + tilen * 32;
#pragma unroll
            for (int er = 0; er < 2; er++)
                pfL2(p + (size_t)(row0 + rb + er * 8) * G);
        }

        // warp-local staging: warp stages ONLY its 16 rows
        auto stageA = [&](int ac) {
            int grp = ac >> 3, g = ac & 7;
            const hf* src = agrp[grp] + (size_t)(row0 + warp * 16) * H + g * 64;
            uint32_t st = rbase + (uint32_t)((ac & 3) * ASTG_B + warp * 2048);
#pragma unroll
            for (int u = 0; u < 4; u++) {
                int id = lane + u * 32;        // 0..127
                int r = id >> 3, k = id & 7;
                cp16u(st + (uint32_t)(r * 128 + ((k ^ (r & 7)) * 16)),
                      src + (size_t)r * H + k * 8);
            }
        };

        auto body = [&](int ac, uint32_t segP, float (&aP)[4][4],
                        uint32_t segQ, float (&aQ)[4][4], bool two) {
            CP_WAIT2();
            __syncwarp();
            if (ac + 3 < NCA) stageA(ac + 3);
            CP_COMMIT();
            uint32_t sbA = rbase + (uint32_t)((ac & 3) * ASTG_B);
            int g = ac & 7;
            uint32_t sbP = wbase + segP * WSEG_B + (uint32_t)(g * 4096);
            uint32_t sbQ = wbase + segQ * WSEG_B + (uint32_t)(g * 4096);
#pragma unroll
            for (int sub = 0; sub < 4; sub++) {
                uint32_t a[4];
                int aseg = (sub * 2 + ahalf) ^ (arow & 7);
                ldm4(sbA + (uint32_t)(arow * 128 + aseg * 16), a);
                int bs0 = (sub * 2 + bhalf) ^ (nrl & 7);
                int bs1 = (sub * 2 + bhalf) ^ ((nrl + 16) & 7);
                uint32_t b0[4], b1[4];
                ldm4(sbP + (uint32_t)(nrl * 128 + bs0 * 16), b0);
                ldm4(sbP + (uint32_t)((nrl + 16) * 128 + bs1 * 16), b1);
                if (two) {
                    uint32_t c0[4], c1[4];
                    ldm4(sbQ + (uint32_t)(nrl * 128 + bs0 * 16), c0);
                    ldm4(sbQ + (uint32_t)((nrl + 16) * 128 + bs1 * 16), c1);
                    mma16816(aP[0], a, b0[0], b0[1]);
                    mma16816(aQ[0], a, c0[0], c0[1]);
                    mma16816(aP[1], a, b0[2], b0[3]);
                    mma16816(aQ[1], a, c0[2], c0[3]);
                    mma16816(aP[2], a, b1[0], b1[1]);
                    mma16816(aQ[2], a, c1[0], c1[1]);
                    mma16816(aP[3], a, b1[2], b1[3]);
                    mma16816(aQ[3], a, c1[2], c1[3]);
                } else {
                    mma16816(aP[0], a, b0[0], b0[1]);
                    mma16816(aP[1], a, b0[2], b0[3]);
                    mma16816(aP[2], a, b1[0], b1[1]);
                    mma16816(aP[3], a, b1[2], b1[3]);
                }
            }
        };

        // cell update for layer l at timestep t from accumulator A
        auto ew = [&](int l, int t, float (&A)[4][4]) {
            if (t < 0 || t >= T1) return;
            float add[4][2][2];   // [gate][er][ej]
            if (l == 0) {
                const float* p = g_pre0 + (size_t)t * B * G + tilen * 32;
#pragma unroll
                for (int er = 0; er < 2; er++) {
                    const float* pr = p + (size_t)(row0 + rb + er * 8) * G;
#pragma unroll
                    for (int q = 0; q < 4; q++) {
                        float2 v = *(const float2*)(pr + q * 8 + j0);
                        add[q][er][0] = v.x;
                        add[q][er][1] = v.y;
                    }
                }
            } else {
#pragma unroll
                for (int q = 0; q < 4; q++) {
                    float v0 = sbias[l - 1][q * 8 + j0];
                    float v1 = sbias[l - 1][q * 8 + j0 + 1];
                    add[q][0][0] = add[q][1][0] = v0;
                    add[q][0][1] = add[q][1][1] = v1;
                }
            }
#pragma unroll
            for (int er = 0; er < 2; er++) {
                hf h2v[2];
                float hnf[2];
#pragma unroll
                for (int ej = 0; ej < 2; ej++) {
                    int e = er * 2 + ej;
                    float gi = A[0][e] + add[0][er][ej];
                    float gf = A[1][e] + add[1][er][ej];
                    float gg = A[2][e] + add[2][er][ej];
                    float go = A[3][e] + add[3][er][ej];
                    float i_ = sigm(gi), f_ = sigm(gf);
                    float g_ = tanhf(gg), o_ = sigm(go);
                    float cn = f_ * cst[l][e] + i_ * g_;
                    float hn = o_ * tanhf(cn);
                    cst[l][e] = cn;
                    h2v[ej] = __float2half(hn);
                    hnf[ej] = hn;
                }
                int row = row0 + rb + er * 8;
                *(__half2*)&g_h[np][l][(size_t)row * H + colbase + j0] =
                    *(__half2*)h2v;
                if (l == NL - 1)
                    *(float2*)(out + OUT_ENC + (size_t)row * T1 * H
                               + (size_t)t * H + colbase + j0) =
                        make_float2(hnf[0], hnf[1]);
            }
        };

        float acc0[4][4] = {}, acc1[4][4] = {}, acc2[4][4] = {};
        stageA(0);
        CP_COMMIT();
        stageA(1);
        CP_COMMIT();
        stageA(2);
        CP_COMMIT();
        // group 0: A=h0 -> Whh0(acc0) + Wih1(acc1)
        for (int ac = 0; ac < 8; ac++)   body(ac, 0u, acc0, 2u, acc1, true);
        ew(0, w, acc0);                 // acc0 complete; overlap with group 1
        // group 1: A=h1 -> Whh1(acc1) + Wih2(acc2)
        for (int ac = 8; ac < 16; ac++)  body(ac, 1u, acc1, 4u, acc2, true);
        ew(1, w - 1, acc1);             // acc1 complete; overlap with group 2
        // group 2: A=h2 -> Whh2(acc2)
        for (int ac = 16; ac < 24; ac++) body(ac, 3u, acc2, 3u, acc2, false);
        ew(2, w - 2, acc2);             // only this ew sits on the wave tail

        gbarh(++gen, m);
    }
}

// ---------------------------------------------------------------------------
extern "C" void kernel_launch(void* const* d_in, const int* in_sizes, int n_in,
                              void* d_out, int out_size) {
    const float* x   = (const float*)d_in[0];
    const float* wih = (const float*)d_in[1];
    const float* whh = (const float*)d_in[2];
    const float* bih = (const float*)d_in[3];
    const float* bhh = (const float*)d_in[4];
    const float* aw  = (const float*)d_in[5];
    float* out = (float*)d_out;

    split_w_kernel<<<(NL * GH + 255) / 256, 256>>>(wih, whh);
    attn_kernel<<<B, 512>>>(x, aw, out);
    dim3 pgrid(T1 * 4, G / 64);
    pre_gemm_kernel<<<pgrid, NT>>>(bih, bhh);
    lstm_kernel<<<GRID, NT>>>(bih, bhh, out);
}

// round 17
// speedup vs baseline: 1.0657x; 1.0136x over previous
#include <cuda_runtime.h>
#include <cuda_fp16.h>
#include <math.h>
#include <stdint.h>

#define B   256
#define T1  127
#define D   512
#define H   512
#define G   2048
#define NL  3
#define GH  (G * H)
#define OUT_ENC ((size_t)B * T1 * D)

#define GRID 128
#define NT   256

typedef __half hf;

// ---------------------------------------------------------------------------
// Scratch
// ---------------------------------------------------------------------------
__device__ float g_pre0[(size_t)T1 * B * G];   // [t][b][tilen*32 + q*8 + j]
__device__ hf g_h[2][NL][B * H];               // wave-parity double buffer
__device__ hf g_wih[NL * GH];
__device__ hf g_whh[NL * GH];
__device__ hf g_x[(size_t)B * T1 * D];
__device__ unsigned g_flagsh[GRID];
__device__ unsigned g_relh[2];

__device__ __forceinline__ float sigm(float x) { return 1.f / (1.f + expf(-x)); }

// ---------------------------------------------------------------------------
// Per-half grid barrier: the two m-halves (64 CTAs each) are independent.
// ---------------------------------------------------------------------------
__device__ __forceinline__ void gbarh(unsigned gen, int m) {
    __syncthreads();
    if (threadIdx.x == 0) {
        __threadfence();
        ((volatile unsigned*)g_flagsh)[blockIdx.x] = gen;
    }
    if ((blockIdx.x & 63) == 0) {
        if (threadIdx.x < 64)
            while ((int)(((volatile unsigned*)g_flagsh)[(blockIdx.x & 64)
                         + threadIdx.x] - gen) < 0) {}
        __syncthreads();
        if (threadIdx.x == 0) {
            __threadfence();
            *(volatile unsigned*)&g_relh[m] = gen;
        }
    }
    while ((int)(*(volatile unsigned*)&g_relh[m] - gen) < 0) {}
    __threadfence();
    __syncthreads();
}

// ---------------------------------------------------------------------------
__device__ __forceinline__ void cp16u(uint32_t dst, const hf* src) {
    asm volatile("cp.async.cg.shared.global [%0], [%1], 16;" :: "r"(dst), "l"(src));
}
#define CP_COMMIT()  asm volatile("cp.async.commit_group;" ::: "memory")
#define CP_WAIT1()   asm volatile("cp.async.wait_group 1;" ::: "memory")
#define CP_WAIT2()   asm volatile("cp.async.wait_group 2;" ::: "memory")
#define CP_WAITALL() asm volatile("cp.async.wait_group 0;" ::: "memory")

__device__ __forceinline__ void ldm4(uint32_t addr, uint32_t r[4]) {
    asm volatile("ldmatrix.sync.aligned.m8n8.x4.shared.b16 {%0,%1,%2,%3}, [%4];"
                 : "=r"(r[0]), "=r"(r[1]), "=r"(r[2]), "=r"(r[3]) : "r"(addr));
}
__device__ __forceinline__ void mma16816(float c[4], const uint32_t a[4],
                                         uint32_t b0, uint32_t b1) {
    asm volatile(
        "mma.sync.aligned.m16n8k16.row.col.f32.f16.f16.f32 "
        "{%0,%1,%2,%3},{%4,%5,%6,%7},{%8,%9},{%0,%1,%2,%3};"
        : "+f"(c[0]), "+f"(c[1]), "+f"(c[2]), "+f"(c[3])
        : "r"(a[0]), "r"(a[1]), "r"(a[2]), "r"(a[3]), "r"(b0), "r"(b1));
}
__device__ __forceinline__ void pfL2(const void* p) {
    asm volatile("prefetch.global.L2 [%0];" :: "l"(p));
}

// ---------------------------------------------------------------------------
__global__ void split_w_kernel(const float* __restrict__ wih,
                               const float* __restrict__ whh) {
    int idx = blockIdx.x * blockDim.x + threadIdx.x;
    if (idx >= NL * GH) return;
    g_wih[idx] = __float2half(wih[idx]);
    g_whh[idx] = __float2half(whh[idx]);
}

// ---------------------------------------------------------------------------
// attn[b,d] = softmax_d( sum_t x[b,t,d]*attn_w[2H+t] )  — time-invariant.
// ---------------------------------------------------------------------------
__global__ void attn_kernel(const float* __restrict__ x, const float* __restrict__ aw,
                            float* __restrict__ out) {
    __shared__ float saw[T1];
    __shared__ float red[512];
    int b = blockIdx.x, d = threadIdx.x;
    if (d < T1) saw[d] = aw[2 * H + d];
    __syncthreads();
    const float* xb = x + (size_t)b * T1 * D;
    float acc = 0.f;
    for (int t = 0; t < T1; t++) acc += xb[(size_t)t * D + d] * saw[t];
    red[d] = acc;
    __syncthreads();
    for (int s = 256; s > 0; s >>= 1) {
        if (d < s) red[d] = fmaxf(red[d], red[d + s]);
        __syncthreads();
    }
    float mx = red[0];
    __syncthreads();
    float e = expf(acc - mx);
    red[d] = e;
    __syncthreads();
    for (int s = 256; s > 0; s >>= 1) {
        if (d < s) red[d] += red[d + s];
        __syncthreads();
    }
    float a = e / red[0];
    float* ob = out + (size_t)b * T1 * D;
    for (int t = 0; t < T1; t++) {
        float w = a * xb[(size_t)t * D + d];
        ob[(size_t)t * D + d] = w;
        g_x[(size_t)b * T1 * D + (size_t)t * D + d] = __float2half(w);
    }
}

// ---------------------------------------------------------------------------
// pre_gemm v2 — 128x128 tiles, 8 warps as 4x2 (warp tile 32x64).
// B-LDSM redundancy 4 (was 8), A redundancy 2: 3x port efficiency.
// Writes pre0 directly in the lstm gather layout:
//   gate col gc = q*512 + tilec*32 + j32  ->  idx = (tilec*4+(j32>>3))*32+q*8+(j32&7)
// ---------------------------------------------------------------------------
#define STG2_B 32768   // A plane 16KB + B plane 16KB per stage

__global__ void __launch_bounds__(NT) pre_gemm_kernel(const float* __restrict__ bih,
                                                      const float* __restrict__ bhh) {
    __shared__ __align__(128) char ring[3 * STG2_B];
    const int tstep = blockIdx.x >> 1;
    const int b0    = (blockIdx.x & 1) * 128;
    const int tilec = blockIdx.y;              // 0..15 (32 cols per gate quadrant)
    const int tid  = threadIdx.x;
    const int lane = tid & 31, warp = tid >> 5;
    const int wr = warp >> 1, wc = warp & 1;
    const int arow  = wr * 32 + (lane & 15);
    const int ahalf = lane >> 4;
    const int nrl   = wc * 64 + ((lane >> 4) << 3) + (lane & 7);
    const int bhalf = (lane >> 3) & 1;
    const uint32_t sbase = (uint32_t)__cvta_generic_to_shared(ring);
    const hf* A0 = g_x + (size_t)tstep * D + (size_t)b0 * (T1 * D);

    auto stage2 = [&](int kc, uint32_t st) {
#pragma unroll
        for (int u = 0; u < 8; u++) {
            int id = tid + u * NT;             // 0..2047
            int pl = id >> 10, rm = id & 1023;
            int r = rm >> 3, s = rm & 7;
            uint32_t dst = st + (uint32_t)(pl * 16384 + r * 128
                          + ((s ^ (r & 7)) * 16));
            const hf* sp;
            if (pl == 0) {
                sp = A0 + (size_t)r * (T1 * D) + kc * 64 + s * 8;
            } else {
                int wrow = ((r >> 5) << 9) + tilec * 32 + (r & 31);
                sp = g_wih + (size_t)wrow * 512 + kc * 64 + s * 8;
            }
            cp16u(dst, sp);
        }
    };

    float acc[2][8][4] = {};
    stage2(0, sbase);
    CP_COMMIT();
    stage2(1, sbase + STG2_B);
    CP_COMMIT();
    for (int kc = 0; kc < 8; kc++) {
        CP_WAIT1();
        __syncthreads();
        if (kc + 2 < 8)
            stage2(kc + 2, sbase + (uint32_t)(((kc + 2) % 3) * STG2_B));
        CP_COMMIT();

        const uint32_t sb = sbase + (uint32_t)((kc % 3) * STG2_B);
#pragma unroll
        for (int sub = 0; sub < 4; sub++) {
            int aseg = (sub * 2 + ahalf) ^ (arow & 7);
            uint32_t a0[4], a1[4];
            ldm4(sb + (uint32_t)(arow * 128 + aseg * 16), a0);
            ldm4(sb + (uint32_t)((arow + 16) * 128 + aseg * 16), a1);
            int bseg = (sub * 2 + bhalf) ^ (nrl & 7);
            uint32_t b0r[4], b1r[4], b2r[4], b3r[4];
            ldm4(sb + (uint32_t)(16384 + nrl * 128 + bseg * 16), b0r);
            ldm4(sb + (uint32_t)(16384 + (nrl + 16) * 128 + bseg * 16), b1r);
            ldm4(sb + (uint32_t)(16384 + (nrl + 32) * 128 + bseg * 16), b2r);
            ldm4(sb + (uint32_t)(16384 + (nrl + 48) * 128 + bseg * 16), b3r);
            mma16816(acc[0][0], a0, b0r[0], b0r[1]);
            mma16816(acc[1][0], a1, b0r[0], b0r[1]);
            mma16816(acc[0][1], a0, b0r[2], b0r[3]);
            mma16816(acc[1][1], a1, b0r[2], b0r[3]);
            mma16816(acc[0][2], a0, b1r[0], b1r[1]);
            mma16816(acc[1][2], a1, b1r[0], b1r[1]);
            mma16816(acc[0][3], a0, b1r[2], b1r[3]);
            mma16816(acc[1][3], a1, b1r[2], b1r[3]);
            mma16816(acc[0][4], a0, b2r[0], b2r[1]);
            mma16816(acc[1][4], a1, b2r[0], b2r[1]);
            mma16816(acc[0][5], a0, b2r[2], b2r[3]);
            mma16816(acc[1][5], a1, b2r[2], b2r[3]);
            mma16816(acc[0][6], a0, b3r[0], b3r[1]);
            mma16816(acc[1][6], a1, b3r[0], b3r[1]);
            mma16816(acc[0][7], a0, b3r[2], b3r[3]);
            mma16816(acc[1][7], a1, b3r[2], b3r[3]);
        }
    }
    __syncthreads();

    size_t base = (size_t)tstep * B * G;
#pragma unroll
    for (int mt = 0; mt < 2; mt++)
#pragma unroll
        for (int nt = 0; nt < 8; nt++)
#pragma unroll
            for (int e = 0; e < 4; e++) {
                int r = wr * 32 + mt * 16 + (lane >> 2) + ((e >> 1) ? 8 : 0);
                int c = wc * 64 + nt * 8 + (lane & 3) * 2 + (e & 1);
                int q = c >> 5, j32 = c & 31;
                int bcol = (q << 9) + tilec * 32 + j32;
                int idx = (tilec * 4 + (j32 >> 3)) * 32 + q * 8 + (j32 & 7);
                g_pre0[base + (size_t)(b0 + r) * G + idx] =
                    acc[mt][nt][e] + bih[bcol] + bhh[bcol];
            }
}

// ---------------------------------------------------------------------------
// Persistent wavefront kernel — FROZEN R16 winner (8 warps, 16-row warp
// tiles, per-warp independent pipelines, persistent SMEM weights, 4-slot
// lookahead-3 ring, per-half barriers, interleaved cell updates).
// ---------------------------------------------------------------------------
#define NCA    24
#define WSEG_B 32768
#define ASTG_B 16384

__global__ void __launch_bounds__(NT, 1) lstm_kernel(const float* __restrict__ bih,
                                                     const float* __restrict__ bhh,
                                                     float* __restrict__ out) {
    __shared__ __align__(128) char wsm[5 * WSEG_B];    // 160KB persistent weights
    __shared__ __align__(128) char ring[4 * ASTG_B];   // 64KB A ring (4 slots)
    __shared__ float sbias[2][32];

    const int tid = threadIdx.x;
    const int warp = tid >> 5, lane = tid & 31;
    const int m     = blockIdx.x >> 6;        // 0..1 (independent halves)
    const int tilen = blockIdx.x & 63;        // 0..63
    const int row0    = m * 128;
    const int colbase = tilen * 8;
    const uint32_t wbase = (uint32_t)__cvta_generic_to_shared(wsm);
    const uint32_t rbase = (uint32_t)__cvta_generic_to_shared(ring);

    unsigned gen = *(volatile unsigned*)&g_relh[m];

    // zero both h parities for THIS half's rows (boundary waves read zeros)
    {
        const int HALF_E = 128 * H;
        for (int idx = (blockIdx.x & 63) * NT + tid; idx < 2 * NL * HALF_E;
             idx += 64 * NT) {
            int pl = idx / HALF_E;
            int rm = idx % HALF_E;
            ((hf*)g_h)[(size_t)pl * (B * H) + (size_t)row0 * H + rm] =
                __float2half(0.f);
        }
    }
    if (tid < 64) {
        int l = tid >> 5, c = tid & 31;
        int bcol = (l + 1) * G + ((c >> 3) << 9) + colbase + (c & 7);
        sbias[l][c] = bih[bcol] + bhh[bcol];
    }

    // one-time persistent weight load
    // seg: 0=Whh0 1=Whh1 2=Wih1 3=Whh2 4=Wih2 ; layout [seg][kchunk8][32r][64k]
    {
        const hf* wsrc[5] = { g_whh, g_whh + GH, g_wih + GH,
                              g_whh + 2 * GH, g_wih + 2 * GH };
#pragma unroll
        for (int it = 0; it < 40; it++) {
            int id = tid + it * NT;          // 0..10239
            int s   = id >> 11;
            int rem = id & 2047;
            int c = rem >> 8;
            int r = (rem >> 3) & 31;
            int k = rem & 7;
            int wrow = ((r >> 3) << 9) + colbase + (r & 7);
            uint32_t dst = wbase + (uint32_t)(s * WSEG_B + c * 4096 + r * 128
                          + ((k ^ (r & 7)) * 16));
            cp16u(dst, wsrc[s] + (size_t)wrow * 512 + c * 64 + k * 8);
        }
        CP_COMMIT();
        CP_WAITALL();
        __syncthreads();
    }

    float cst[NL][4];
#pragma unroll
    for (int l = 0; l < NL; l++)
#pragma unroll
        for (int e = 0; e < 4; e++) cst[l][e] = 0.f;

    const int arow  = warp * 16 + (lane & 15);
    const int ahalf = lane >> 4;
    const int nrl   = ((lane >> 4) << 3) + (lane & 7);
    const int bhalf = (lane >> 3) & 1;
    const int rb = warp * 16 + (lane >> 2);
    const int j0 = (lane & 3) * 2;

    gbarh(++gen, m);

    for (int w = 0; w < T1 + 2; w++) {
        const int np = w & 1, op = np ^ 1;
        const hf* agrp[3] = { g_h[op][0], g_h[op][1], g_h[op][2] };

        // prefetch pre0[t=w] rows into L2 (read by ew(l0) mid-wave)
        if (w < T1) {
            const float* p = g_pre0 + (size_t)w * B * G + tilen * 32;
#pragma unroll
            for (int er = 0; er < 2; er++)
                pfL2(p + (size_t)(row0 + rb + er * 8) * G);
        }

        // warp-local staging: warp stages ONLY its 16 rows
        auto stageA = [&](int ac) {
            int grp = ac >> 3, g = ac & 7;
            const hf* src = agrp[grp] + (size_t)(row0 + warp * 16) * H + g * 64;
            uint32_t st = rbase + (uint32_t)((ac & 3) * ASTG_B + warp * 2048);
#pragma unroll
            for (int u = 0; u < 4; u++) {
                int id = lane + u * 32;        // 0..127
                int r = id >> 3, k = id & 7;
                cp16u(st + (uint32_t)(r * 128 + ((k ^ (r & 7)) * 16)),
                      src + (size_t)r * H + k * 8);
            }
        };

        auto body = [&](int ac, uint32_t segP, float (&aP)[4][4],
                        uint32_t segQ, float (&aQ)[4][4], bool two) {
            CP_WAIT2();
            __syncwarp();
            if (ac + 3 < NCA) stageA(ac + 3);
            CP_COMMIT();
            uint32_t sbA = rbase + (uint32_t)((ac & 3) * ASTG_B);
            int g = ac & 7;
            uint32_t sbP = wbase + segP * WSEG_B + (uint32_t)(g * 4096);
            uint32_t sbQ = wbase + segQ * WSEG_B + (uint32_t)(g * 4096);
#pragma unroll
            for (int sub = 0; sub < 4; sub++) {
                uint32_t a[4];
                int aseg = (sub * 2 + ahalf) ^ (arow & 7);
                ldm4(sbA + (uint32_t)(arow * 128 + aseg * 16), a);
                int bs0 = (sub * 2 + bhalf) ^ (nrl & 7);
                int bs1 = (sub * 2 + bhalf) ^ ((nrl + 16) & 7);
                uint32_t b0[4], b1[4];
                ldm4(sbP + (uint32_t)(nrl * 128 + bs0 * 16), b0);
                ldm4(sbP + (uint32_t)((nrl + 16) * 128 + bs1 * 16), b1);
                if (two) {
                    uint32_t c0[4], c1[4];
                    ldm4(sbQ + (uint32_t)(nrl * 128 + bs0 * 16), c0);
                    ldm4(sbQ + (uint32_t)((nrl + 16) * 128 + bs1 * 16), c1);
                    mma16816(aP[0], a, b0[0], b0[1]);
                    mma16816(aQ[0], a, c0[0], c0[1]);
                    mma16816(aP[1], a, b0[2], b0[3]);
                    mma16816(aQ[1], a, c0[2], c0[3]);
                    mma16816(aP[2], a, b1[0], b1[1]);
                    mma16816(aQ[2], a, c1[0], c1[1]);
                    mma16816(aP[3], a, b1[2], b1[3]);
                    mma16816(aQ[3], a, c1[2], c1[3]);
                } else {
                    mma16816(aP[0], a, b0[0], b0[1]);
                    mma16816(aP[1], a, b0[2], b0[3]);
                    mma16816(aP[2], a, b1[0], b1[1]);
                    mma16816(aP[3], a, b1[2], b1[3]);
                }
            }
        };

        // cell update for layer l at timestep t from accumulator A
        auto ew = [&](int l, int t, float (&A)[4][4]) {
            if (t < 0 || t >= T1) return;
            float add[4][2][2];   // [gate][er][ej]
            if (l == 0) {
                const float* p = g_pre0 + (size_t)t * B * G + tilen * 32;
#pragma unroll
                for (int er = 0; er < 2; er++) {
                    const float* pr = p + (size_t)(row0 + rb + er * 8) * G;
#pragma unroll
                    for (int q = 0; q < 4; q++) {
                        float2 v = *(const float2*)(pr + q * 8 + j0);
                        add[q][er][0] = v.x;
                        add[q][er][1] = v.y;
                    }
                }
            } else {
#pragma unroll
                for (int q = 0; q < 4; q++) {
                    float v0 = sbias[l - 1][q * 8 + j0];
                    float v1 = sbias[l - 1][q * 8 + j0 + 1];
                    add[q][0][0] = add[q][1][0] = v0;
                    add[q][0][1] = add[q][1][1] = v1;
                }
            }
#pragma unroll
            for (int er = 0; er < 2; er++) {
                hf h2v[2];
                float hnf[2];
#pragma unroll
                for (int ej = 0; ej < 2; ej++) {
                    int e = er * 2 + ej;
                    float gi = A[0][e] + add[0][er][ej];
                    float gf = A[1][e] + add[1][er][ej];
                    float gg = A[2][e] + add[2][er][ej];
                    float go = A[3][e] + add[3][er][ej];
                    float i_ = sigm(gi), f_ = sigm(gf);
                    float g_ = tanhf(gg), o_ = sigm(go);
                    float cn = f_ * cst[l][e] + i_ * g_;
                    float hn = o_ * tanhf(cn);
                    cst[l][e] = cn;
                    h2v[ej] = __float2half(hn);
                    hnf[ej] = hn;
                }
                int row = row0 + rb + er * 8;
                *(__half2*)&g_h[np][l][(size_t)row * H + colbase + j0] =
                    *(__half2*)h2v;
                if (l == NL - 1)
                    *(float2*)(out + OUT_ENC + (size_t)row * T1 * H
                               + (size_t)t * H + colbase + j0) =
                        make_float2(hnf[0], hnf[1]);
            }
        };

        float acc0[4][4] = {}, acc1[4][4] = {}, acc2[4][4] = {};
        stageA(0);
        CP_COMMIT();
        stageA(1);
        CP_COMMIT();
        stageA(2);
        CP_COMMIT();
        // group 0: A=h0 -> Whh0(acc0) + Wih1(acc1)
        for (int ac = 0; ac < 8; ac++)   body(ac, 0u, acc0, 2u, acc1, true);
        ew(0, w, acc0);                 // acc0 complete; overlap with group 1
        // group 1: A=h1 -> Whh1(acc1) + Wih2(acc2)
        for (int ac = 8; ac < 16; ac++)  body(ac, 1u, acc1, 4u, acc2, true);
        ew(1, w - 1, acc1);             // acc1 complete; overlap with group 2
        // group 2: A=h2 -> Whh2(acc2)
        for (int ac = 16; ac < 24; ac++) body(ac, 3u, acc2, 3u, acc2, false);
        ew(2, w - 2, acc2);             // only this ew sits on the wave tail

        gbarh(++gen, m);
    }
}

// ---------------------------------------------------------------------------
extern "C" void kernel_launch(void* const* d_in, const int* in_sizes, int n_in,
                              void* d_out, int out_size) {
    const float* x   = (const float*)d_in[0];
    const float* wih = (const float*)d_in[1];
    const float* whh = (const float*)d_in[2];
    const float* bih = (const float*)d_in[3];
    const float* bhh = (const float*)d_in[4];
    const float* aw  = (const float*)d_in[5];
    float* out = (float*)d_out;

    split_w_kernel<<<(NL * GH + 255) / 256, 256>>>(wih, whh);
    attn_kernel<<<B, 512>>>(x, aw, out);
    dim3 pgrid(T1 * 2, 16);
    pre_gemm_kernel<<<pgrid, NT>>>(bih, bhh);
    lstm_kernel<<<GRID, NT>>>(bih, bhh, out);
}